// round 2
// baseline (speedup 1.0000x reference)
#include <cuda_runtime.h>
#include <math.h>

#define TS 63
#define B 32
#define S 256
#define H 512
#define E 512
#define V 32000
#define G4 2048

// ------------------------- device scratch (no allocs allowed) ---------------
__device__ float g_h[2][B*H];
__device__ float g_c[2][B*H];
__device__ float g_emb[TS][B*E];
__device__ float g_dec[B*H];       // input_feed / dec_out
__device__ float g_q[B*H];
__device__ float g_ctx[B*H];
__device__ float g_part0[3][G4*B];
__device__ float g_part1[2][G4*B];
__device__ float g_WaT[H*H];
__device__ float g_sumZ[B];

// ------------------------- warp GEMV helpers --------------------------------
// Each warp computes dot(W_row, x_b) for all 32 batches. K == 512 fixed.
__device__ __forceinline__ void warp_gemv_acc(const float* __restrict__ Wrow,
                                              const float* __restrict__ X,
                                              float acc[B]) {
    const int lane = threadIdx.x & 31;
#pragma unroll
    for (int kk = 0; kk < 4; kk++) {
        const int k = kk*128 + lane*4;
        const float4 w = *reinterpret_cast<const float4*>(Wrow + k);
#pragma unroll
        for (int b = 0; b < B; b++) {
            const float4 x = *reinterpret_cast<const float4*>(X + b*H + k);
            acc[b] += w.x*x.x + w.y*x.y + w.z*x.z + w.w*x.w;
        }
    }
}

// Reduce 32 per-lane partials so that lane b ends with sum over lanes of acc[b].
// sm must be 32*33 floats, private to this warp.
__device__ __forceinline__ float warp_reduce_b(float acc[B], float* sm) {
    const int lane = threadIdx.x & 31;
#pragma unroll
    for (int b = 0; b < B; b++) sm[b*33 + lane] = acc[b];
    __syncwarp();
    float s = 0.f;
#pragma unroll
    for (int j = 0; j < 32; j++) s += sm[lane*33 + j];
    return s;
}

// ------------------------- kernels ------------------------------------------
__global__ void __launch_bounds__(256) k_init(const float* __restrict__ eh,
                                              const float* __restrict__ ec,
                                              const float* __restrict__ Wa) {
    int idx = blockIdx.x*256 + threadIdx.x;          // grid covers H*H
    if (idx < 2*B*H) { (&g_h[0][0])[idx] = eh[idx]; (&g_c[0][0])[idx] = ec[idx]; }
    if (idx < B*H)   g_dec[idx] = 0.f;
    if (idx < H*H)   { int h = idx / H; int k = idx - h*H; g_WaT[k*H + h] = Wa[idx]; }
}

__global__ void __launch_bounds__(256) k_embed(const int* __restrict__ tgt,
                                               const float* __restrict__ et) {
    int idx = blockIdx.x*256 + threadIdx.x;          // < TS*B*E
    int e = idx & (E - 1);
    int r = idx >> 9;                                 // t*B + b
    int tok = tgt[r];
    (&g_emb[0][0])[idx] = et[(size_t)tok*E + e];
}

__global__ void __launch_bounds__(256) k_gemm0(const float* __restrict__ Wx0,
                                               const float* __restrict__ Wh0, int t) {
    __shared__ float sm[8][33*32];
    const int warp = threadIdx.x >> 5, lane = threadIdx.x & 31;
    const int n = blockIdx.x*8 + warp;                // 0..2047
    const int p = blockIdx.y;                         // 0..2
    const float* Wrow; const float* X;
    if (p == 0)      { Wrow = Wx0 + (size_t)n*1024;        X = g_emb[t]; }
    else if (p == 1) { Wrow = Wx0 + (size_t)n*1024 + 512;  X = g_dec;    }
    else             { Wrow = Wh0 + (size_t)n*512;         X = g_h[0];   }
    float acc[B] = {};
    warp_gemv_acc(Wrow, X, acc);
    float s = warp_reduce_b(acc, sm[warp]);
    g_part0[p][n*B + lane] = s;
}

__global__ void __launch_bounds__(256) k_gemm1(const float* __restrict__ Wx1,
                                               const float* __restrict__ Wh1) {
    __shared__ float sm[8][33*32];
    const int warp = threadIdx.x >> 5, lane = threadIdx.x & 31;
    const int n = blockIdx.x*8 + warp;
    const int p = blockIdx.y;                         // 0..1
    const float* Wrow; const float* X;
    if (p == 0) { Wrow = Wx1 + (size_t)n*512; X = g_h[0]; }   // h0 (new)
    else        { Wrow = Wh1 + (size_t)n*512; X = g_h[1]; }   // h1 (old)
    float acc[B] = {};
    warp_gemv_acc(Wrow, X, acc);
    float s = warp_reduce_b(acc, sm[warp]);
    g_part1[p][n*B + lane] = s;
}

__device__ __forceinline__ float sigm(float x) { return 1.f/(1.f+expf(-x)); }

__global__ void __launch_bounds__(256) k_act(int which, int nparts,
                                             const float* __restrict__ bias,
                                             int layer, int zeroSum) {
    int idx = blockIdx.x*256 + threadIdx.x;           // < B*H
    const float* parts = which ? &g_part1[0][0] : &g_part0[0][0];
    int b = idx & 31, j = idx >> 5;                   // j: hidden index
    float gi = bias[j], gf = bias[512+j], gg = bias[1024+j], go = bias[1536+j];
    for (int p = 0; p < nparts; p++) {
        const float* pp = parts + (size_t)p*(G4*B);
        gi += pp[(j       )*B + b];
        gf += pp[(512 + j )*B + b];
        gg += pp[(1024 + j)*B + b];
        go += pp[(1536 + j)*B + b];
    }
    float c  = g_c[layer][b*H + j];
    float cn = sigm(gf)*c + sigm(gi)*tanhf(gg);
    g_c[layer][b*H + j] = cn;
    g_h[layer][b*H + j] = sigm(go)*tanhf(cn);
    if (zeroSum && idx < B) g_sumZ[idx] = 0.f;
}

__global__ void __launch_bounds__(256) k_q() {
    __shared__ float sm[8][33*32];
    const int warp = threadIdx.x >> 5, lane = threadIdx.x & 31;
    const int n = blockIdx.x*8 + warp;                // 0..511
    float acc[B] = {};
    warp_gemv_acc(g_WaT + (size_t)n*H, g_h[1], acc);
    float s = warp_reduce_b(acc, sm[warp]);
    g_q[lane*H + n] = s;
}

__global__ void __launch_bounds__(256) k_attn(const float* __restrict__ mb,
                                              const int* __restrict__ mlen,
                                              float* __restrict__ attn_out, int t) {
    __shared__ float al[S];
    __shared__ float red[256];
    const int b = blockIdx.x;
    const int tid = threadIdx.x, warp = tid >> 5, lane = tid & 31;
    const int len = mlen[b];
    // align[s] = q[b,:] . mb[s,b,:]
    for (int s0 = warp; s0 < S; s0 += 8) {
        const float* m = mb + ((size_t)s0*B + b)*H;
        const float* q = g_q + b*H;
        float a = 0.f;
#pragma unroll
        for (int kk = 0; kk < 4; kk++) {
            int k = kk*128 + lane*4;
            float4 mv = *reinterpret_cast<const float4*>(m + k);
            float4 qv = *reinterpret_cast<const float4*>(q + k);
            a += mv.x*qv.x + mv.y*qv.y + mv.z*qv.z + mv.w*qv.w;
        }
#pragma unroll
        for (int off = 16; off; off >>= 1) a += __shfl_xor_sync(0xffffffffu, a, off);
        if (lane == 0) al[s0] = (s0 < len) ? a : -1.0e9f;
    }
    __syncthreads();
    // softmax over S == 256 (one element per thread)
    float v = al[tid];
    red[tid] = v; __syncthreads();
    for (int o = 128; o; o >>= 1) { if (tid < o) red[tid] = fmaxf(red[tid], red[tid+o]); __syncthreads(); }
    float vmax = red[0];
    __syncthreads();
    float e = expf(v - vmax);
    red[tid] = e; __syncthreads();
    for (int o = 128; o; o >>= 1) { if (tid < o) red[tid] += red[tid+o]; __syncthreads(); }
    float p = e / red[0];
    al[tid] = p;
    attn_out[((size_t)t*B + b)*S + tid] = p;
    __syncthreads();
    // ctx[k] = sum_s p[s] * mb[s,b,k]
    for (int k = tid; k < H; k += 256) {
        float acc = 0.f;
#pragma unroll 4
        for (int s = 0; s < S; s++) acc += al[s] * mb[((size_t)s*B + b)*H + k];
        g_ctx[b*H + k] = acc;
    }
}

__global__ void __launch_bounds__(256) k_wc(const float* __restrict__ Wc) {
    __shared__ float sm[8][33*32];
    const int warp = threadIdx.x >> 5, lane = threadIdx.x & 31;
    const int n = blockIdx.x*8 + warp;                // 0..511
    float acc[B] = {};
    warp_gemv_acc(Wc + (size_t)n*1024,       g_ctx,  acc);
    warp_gemv_acc(Wc + (size_t)n*1024 + 512, g_h[1], acc);
    float s = warp_reduce_b(acc, sm[warp]);
    g_dec[lane*H + n] = tanhf(s);
}

__global__ void __launch_bounds__(256) k_gen(const float* __restrict__ Wgen,
                                             const float* __restrict__ bgen,
                                             float* __restrict__ out, int t) {
    __shared__ float sm[8][33*32];
    __shared__ float exs[8][32];
    const int warp = threadIdx.x >> 5, lane = threadIdx.x & 31;
    const int n = blockIdx.x*8 + warp;                // 0..31999
    float acc[B] = {};
    warp_gemv_acc(Wgen + (size_t)n*H, g_dec, acc);
    float s = warp_reduce_b(acc, sm[warp]) + bgen[n];
    out[((size_t)t*B + lane)*V + n] = s;              // raw logit; fixed up by k_lsm
    exs[warp][lane] = expf(s);
    __syncthreads();
    if (warp == 0) {
        float t0 = 0.f;
#pragma unroll
        for (int w = 0; w < 8; w++) t0 += exs[w][lane];
        atomicAdd(&g_sumZ[lane], t0);
    }
}

__global__ void __launch_bounds__(256) k_lsm(float* __restrict__ out, int t) {
    __shared__ float lz;
    const int b = blockIdx.y;
    if (threadIdx.x == 0) lz = logf(g_sumZ[b]);
    __syncthreads();
    int v = blockIdx.x*256 + threadIdx.x;
    out[((size_t)t*B + b)*V + v] -= lz;
}

// ------------------------- launch -------------------------------------------
extern "C" void kernel_launch(void* const* d_in, const int* in_sizes, int n_in,
                              void* d_out, int out_size) {
    const int*   tgt   = (const int*)  d_in[0];
    const float* mb    = (const float*)d_in[1];
    const int*   mlen  = (const int*)  d_in[2];
    const float* enc_h = (const float*)d_in[3];
    const float* enc_c = (const float*)d_in[4];
    const float* emb   = (const float*)d_in[5];
    const float* Wx0   = (const float*)d_in[6];
    const float* Wh0   = (const float*)d_in[7];
    const float* b0    = (const float*)d_in[8];
    const float* Wx1   = (const float*)d_in[9];
    const float* Wh1   = (const float*)d_in[10];
    const float* b1    = (const float*)d_in[11];
    const float* Wa    = (const float*)d_in[12];
    const float* Wc    = (const float*)d_in[13];
    const float* Wgen  = (const float*)d_in[14];
    const float* bgen  = (const float*)d_in[15];

    float* out      = (float*)d_out;
    float* attn_out = out + (size_t)TS*B*V;

    k_init <<<(H*H + 255)/256, 256>>>(enc_h, enc_c, Wa);
    k_embed<<<(TS*B*E)/256, 256>>>(tgt, emb);

    for (int t = 0; t < TS; t++) {
        k_gemm0<<<dim3(G4/8, 3), 256>>>(Wx0, Wh0, t);
        k_act  <<<(B*H)/256, 256>>>(0, 3, b0, 0, 0);
        k_gemm1<<<dim3(G4/8, 2), 256>>>(Wx1, Wh1);
        k_act  <<<(B*H)/256, 256>>>(1, 2, b1, 1, 1);   // also zeroes g_sumZ
        k_q    <<<H/8, 256>>>();
        k_attn <<<B, 256>>>(mb, mlen, attn_out, t);
        k_wc   <<<H/8, 256>>>(Wc);
        k_gen  <<<V/8, 256>>>(Wgen, bgen, out, t);
        k_lsm  <<<dim3(V/256, B), 256>>>(out, t);
    }
}